// round 14
// baseline (speedup 1.0000x reference)
#include <cuda_runtime.h>
#include <cuda_fp16.h>
#include <math.h>

#define T 1024
#define H 2048
#define I_DIM 1024
#define E 32

#define BM 64
#define BK 32
#define PITCH 40   // fp16 elems per smem row (32 + 8 pad)

// Scratch (no allocations allowed -> __device__ globals)
__device__ int    g_count[E];
__device__ int    g_list[E * 2 * T];
__device__ float  g_pairw[T * 2];
__device__ __align__(16) __half g_xf[(size_t)T * H];          // x in fp16, 4MB
__device__ __align__(16) __half g_hbuf[(size_t)T * 2 * I_DIM]; // h in fp16, 4MB

// ---------------------------------------------------------------------------
__global__ void zero_kernel(float* __restrict__ out) {
    int i = blockIdx.x * blockDim.x + threadIdx.x;
    if (i < T * H) out[i] = 0.0f;
    if (i < E) g_count[i] = 0;
}

__global__ void convert_x_kernel(const float* __restrict__ x) {
    int i = blockIdx.x * blockDim.x + threadIdx.x;   // over T*H/2
    float2 v = ((const float2*)x)[i];
    ((__half2*)g_xf)[i] = __float22half2_rn(v);
}

// ---------------------------------------------------------------------------
__global__ __launch_bounds__(128) void router_kernel(
    const float* __restrict__ x, const float* __restrict__ gw) {
    int t = blockIdx.x;
    __shared__ float logits[E];
    int warp = threadIdx.x >> 5;
    int lane = threadIdx.x & 31;
    const float4* xt = (const float4*)(x + (size_t)t * H);

    for (int e = warp; e < E; e += 4) {
        const float4* w = (const float4*)(gw + (size_t)e * H);
        float s = 0.0f;
        #pragma unroll 4
        for (int h = lane; h < H / 4; h += 32) {
            float4 a = xt[h];
            float4 b = w[h];
            s += a.x * b.x + a.y * b.y + a.z * b.z + a.w * b.w;
        }
        #pragma unroll
        for (int o = 16; o; o >>= 1) s += __shfl_xor_sync(0xffffffffu, s, o);
        if (lane == 0) logits[e] = s;
    }
    __syncthreads();

    if (threadIdx.x == 0) {
        float b1 = -1e30f, b2 = -1e30f;
        int i1 = 0, i2 = 0;
        #pragma unroll
        for (int e = 0; e < E; e++) {
            float v = logits[e];
            if (v > b1)      { b2 = b1; i2 = i1; b1 = v; i1 = e; }
            else if (v > b2) { b2 = v; i2 = e; }
        }
        float w1 = 1.0f / (1.0f + expf(b2 - b1));
        float w2 = 1.0f - w1;
        g_pairw[t * 2 + 0] = w1;
        g_pairw[t * 2 + 1] = w2;
        int p1 = atomicAdd(&g_count[i1], 1);
        g_list[i1 * 2 * T + p1] = t * 2 + 0;
        int p2 = atomicAdd(&g_count[i2], 1);
        g_list[i2 * 2 * T + p2] = t * 2 + 1;
    }
}

// ---------------------------------------------------------------------------
__device__ __forceinline__ unsigned smem_u32(const void* p) {
    return (unsigned)__cvta_generic_to_shared(p);
}
__device__ __forceinline__ void ldsm_x4(unsigned addr, unsigned (&r)[4]) {
    asm volatile("ldmatrix.sync.aligned.m8n8.x4.shared.b16 {%0,%1,%2,%3}, [%4];\n"
        : "=r"(r[0]), "=r"(r[1]), "=r"(r[2]), "=r"(r[3]) : "r"(addr));
}
__device__ __forceinline__ void ldsm_x2(unsigned addr, unsigned (&r)[2]) {
    asm volatile("ldmatrix.sync.aligned.m8n8.x2.shared.b16 {%0,%1}, [%2];\n"
        : "=r"(r[0]), "=r"(r[1]) : "r"(addr));
}
__device__ __forceinline__ void mma16816(float (&c)[4], const unsigned (&a)[4],
                                         unsigned b0, unsigned b1) {
    asm volatile(
        "mma.sync.aligned.m16n8k16.row.col.f32.f16.f16.f32 "
        "{%0,%1,%2,%3}, {%4,%5,%6,%7}, {%8,%9}, {%0,%1,%2,%3};\n"
        : "+f"(c[0]), "+f"(c[1]), "+f"(c[2]), "+f"(c[3])
        : "r"(a[0]), "r"(a[1]), "r"(a[2]), "r"(a[3]), "r"(b0), "r"(b1));
}
__device__ __forceinline__ uint2 cvt4(float4 v) {
    __half2 h0 = __float22half2_rn(make_float2(v.x, v.y));
    __half2 h1 = __float22half2_rn(make_float2(v.z, v.w));
    uint2 r;
    r.x = *reinterpret_cast<unsigned*>(&h0);
    r.y = *reinterpret_cast<unsigned*>(&h1);
    return r;
}

// ---------------------------------------------------------------------------
// Gate+Up: M=64 slots x N=32 i-cols (g AND u), K=H. fp16 mma, fp32 accum.
__global__ __launch_bounds__(256) void gateup_kernel(
    const float* __restrict__ Wg, const float* __restrict__ Wu) {
    int e = blockIdx.z;
    int cnt = g_count[e];
    int slot0 = blockIdx.x * BM;
    if (slot0 >= cnt) return;
    int i0 = blockIdx.y * 32;

    __shared__ __align__(16) __half sA[BM * PITCH];
    __shared__ __align__(16) __half sG[32 * PITCH];
    __shared__ __align__(16) __half sU[32 * PITCH];
    __shared__ int spair[BM];

    int tid = threadIdx.x;
    if (tid < BM) {
        int s = slot0 + tid;
        spair[tid] = (s < cnt) ? g_list[e * 2 * T + s] : g_list[e * 2 * T];
    }
    __syncthreads();

    // A: 64 rows x 32 fp16 = 4KB; each thread one uint4 (8 halves)
    int arow = tid >> 2, achk = tid & 3;
    const __half* a1 = g_xf + (size_t)(spair[arow] >> 1) * H + achk * 8;
    int offA = arow * PITCH + achk * 8;
    // weights: 32 rows x 32 fp32 per matrix; each thread one float4 per matrix
    int brow = tid >> 3, bchk = tid & 7;
    const float* gp = Wg + ((size_t)e * I_DIM + i0 + brow) * H + bchk * 4;
    const float* up = Wu + ((size_t)e * I_DIM + i0 + brow) * H + bchk * 4;
    int offB = brow * PITCH + bchk * 4;

    int warp = tid >> 5, lane = tid & 31;
    int wm = warp >> 2;   // 0..1 (32 rows each)
    int wn = warp & 3;    // 0..3 (8 cols each)

    unsigned uA = smem_u32(sA), uG = smem_u32(sG), uU = smem_u32(sU);
    unsigned aoff0 = ((wm * 32 + (lane & 15)) * PITCH + (lane >> 4) * 8) * 2;
    unsigned aoff1 = aoff0 + 16 * PITCH * 2;
    unsigned boff  = ((wn * 8 + (lane & 7)) * PITCH + ((lane >> 3) & 1) * 8) * 2;

    float cg[2][4] = {};
    float cu[2][4] = {};

    // prologue loads
    uint4  va = *(const uint4*)(a1);
    float4 vg = *(const float4*)(gp);
    float4 vu = *(const float4*)(up);

    for (int k0 = 0; k0 < H; k0 += BK) {
        __syncthreads();
        *(uint4*)&sA[offA] = va;
        *(uint2*)&sG[offB] = cvt4(vg);
        *(uint2*)&sU[offB] = cvt4(vu);
        __syncthreads();

        int kn = k0 + BK;
        if (kn < H) {
            va = *(const uint4*)(a1 + kn);
            vg = *(const float4*)(gp + kn);
            vu = *(const float4*)(up + kn);
        }

        #pragma unroll
        for (int ks = 0; ks < 2; ks++) {
            unsigned kb = ks * 32;
            unsigned ah0[4], ah1[4];
            ldsm_x4(uA + aoff0 + kb, ah0);
            ldsm_x4(uA + aoff1 + kb, ah1);
            unsigned bg[2], bu[2];
            ldsm_x2(uG + boff + kb, bg);
            ldsm_x2(uU + boff + kb, bu);

            mma16816(cg[0], ah0, bg[0], bg[1]);
            mma16816(cg[1], ah1, bg[0], bg[1]);
            mma16816(cu[0], ah0, bu[0], bu[1]);
            mma16816(cu[1], ah1, bu[0], bu[1]);
        }
    }

    // epilogue: h = silu(g) * u * combine_weight -> g_hbuf (fp16)
    #pragma unroll
    for (int mi = 0; mi < 2; mi++) {
        #pragma unroll
        for (int half = 0; half < 2; half++) {
            int row = wm * 32 + mi * 16 + (lane >> 2) + half * 8;
            if (slot0 + row < cnt) {
                int pair = spair[row];
                float w = g_pairw[pair];
                int col = i0 + wn * 8 + ((lane & 3) << 1);
                float g0 = cg[mi][half * 2 + 0];
                float g1 = cg[mi][half * 2 + 1];
                float u0 = cu[mi][half * 2 + 0];
                float u1 = cu[mi][half * 2 + 1];
                float h0 = g0 / (1.0f + expf(-g0)) * u0 * w;
                float h1 = g1 / (1.0f + expf(-g1)) * u1 * w;
                *(__half2*)(g_hbuf + (size_t)pair * I_DIM + col) =
                    __floats2half2_rn(h0, h1);
            }
        }
    }
}

// ---------------------------------------------------------------------------
// Down: M=64 slots x N=64 h-cols, K=I. fp16 A from g_hbuf. Scatter-add.
__global__ __launch_bounds__(256) void down_kernel(
    const float* __restrict__ Wd, float* __restrict__ out) {
    int e = blockIdx.z;
    int cnt = g_count[e];
    int slot0 = blockIdx.x * BM;
    if (slot0 >= cnt) return;
    int h0 = blockIdx.y * 64;

    __shared__ __align__(16) __half sA[BM * PITCH];
    __shared__ __align__(16) __half sB[64 * PITCH];
    __shared__ int spair[BM];

    int tid = threadIdx.x;
    if (tid < BM) {
        int s = slot0 + tid;
        spair[tid] = (s < cnt) ? g_list[e * 2 * T + s] : g_list[e * 2 * T];
    }
    __syncthreads();

    int arow = tid >> 2, achk = tid & 3;
    const __half* a1 = g_hbuf + (size_t)spair[arow] * I_DIM + achk * 8;
    int offA = arow * PITCH + achk * 8;
    // B: 64 rows x 32 fp32; each thread two float4 (32B)
    int brow = tid >> 2, bchk = tid & 3;
    const float* b1 = Wd + ((size_t)e * H + h0 + brow) * I_DIM + bchk * 8;
    int offB = brow * PITCH + bchk * 8;

    int warp = tid >> 5, lane = tid & 31;
    int wm = warp >> 2;   // 0..1
    int wn = warp & 3;    // 0..3 (16 cols each)

    unsigned uA = smem_u32(sA), uB = smem_u32(sB);
    unsigned aoff0 = ((wm * 32 + (lane & 15)) * PITCH + (lane >> 4) * 8) * 2;
    unsigned aoff1 = aoff0 + 16 * PITCH * 2;
    unsigned boff = ((wn * 16 + (lane & 7) + ((lane >> 4) & 1) * 8) * PITCH
                     + ((lane >> 3) & 1) * 8) * 2;

    float c[2][2][4] = {};

    // prologue loads
    uint4  va  = *(const uint4*)(a1);
    float4 vb1 = *(const float4*)(b1);
    float4 vb2 = *(const float4*)(b1 + 4);

    for (int k0 = 0; k0 < I_DIM; k0 += BK) {
        __syncthreads();
        *(uint4*)&sA[offA] = va;
        *(uint2*)&sB[offB]     = cvt4(vb1);
        *(uint2*)&sB[offB + 4] = cvt4(vb2);
        __syncthreads();

        int kn = k0 + BK;
        if (kn < I_DIM) {
            va  = *(const uint4*)(a1 + kn);
            vb1 = *(const float4*)(b1 + kn);
            vb2 = *(const float4*)(b1 + kn + 4);
        }

        #pragma unroll
        for (int ks = 0; ks < 2; ks++) {
            unsigned kb = ks * 32;
            unsigned ah0[4], ah1[4];
            ldsm_x4(uA + aoff0 + kb, ah0);
            ldsm_x4(uA + aoff1 + kb, ah1);
            unsigned bh[4];
            ldsm_x4(uB + boff + kb, bh);

            mma16816(c[0][0], ah0, bh[0], bh[1]);
            mma16816(c[0][1], ah0, bh[2], bh[3]);
            mma16816(c[1][0], ah1, bh[0], bh[1]);
            mma16816(c[1][1], ah1, bh[2], bh[3]);
        }
    }

    // epilogue: scatter-add into out[token][h]
    #pragma unroll
    for (int mi = 0; mi < 2; mi++) {
        #pragma unroll
        for (int half = 0; half < 2; half++) {
            int row = wm * 32 + mi * 16 + (lane >> 2) + half * 8;
            if (slot0 + row < cnt) {
                int token = spair[row] >> 1;
                float* orow = out + (size_t)token * H + h0 + wn * 16;
                #pragma unroll
                for (int ni = 0; ni < 2; ni++) {
                    int col = ni * 8 + ((lane & 3) << 1);
                    atomicAdd(&orow[col],     c[mi][ni][half * 2 + 0]);
                    atomicAdd(&orow[col + 1], c[mi][ni][half * 2 + 1]);
                }
            }
        }
    }
}

// ---------------------------------------------------------------------------
extern "C" void kernel_launch(void* const* d_in, const int* in_sizes, int n_in,
                              void* d_out, int out_size) {
    const float* x  = (const float*)d_in[0];
    const float* gw = (const float*)d_in[1];
    const float* Wg = (const float*)d_in[2];
    const float* Wu = (const float*)d_in[3];
    const float* Wd = (const float*)d_in[4];
    float* out = (float*)d_out;

    zero_kernel<<<(T * H + 255) / 256, 256>>>(out);
    convert_x_kernel<<<(T * H / 2) / 256, 256>>>(x);
    router_kernel<<<T, 128>>>(x, gw);
    {
        dim3 grid(T * 2 / BM, I_DIM / 32, E);
        gateup_kernel<<<grid, 256>>>(Wg, Wu);
    }
    {
        dim3 grid(T * 2 / BM, H / 64, E);
        down_kernel<<<grid, 256>>>(Wd, out);
    }
}